// round 10
// baseline (speedup 1.0000x reference)
#include <cuda_runtime.h>
#include <cuda_bf16.h>
#include <mma.h>
#include <cstdint>
#include <math.h>

using namespace nvcuda;
typedef __nv_bfloat16 bf16;

// Problem constants (fixed shapes)
#define TOK   131072      // B*H*W = 8*128*128
#define CDIM  192
#define HID   768
#define QKVN  576
#define NHEAD 6
#define SS    4
#define NWIN  2048        // B * 16 * 16

// GEMM tiling: block 128x192, 8 warps (2m x 4n), warp tile 64x48
#define BM 128
#define BN 192
#define BK 32
#define LDA 40            // bf16 ld, 80B rows
#define LDB 200           // bf16 ld for B (192+8), 400B rows
#define LDC 196           // fp32 ld for 64-row C half (784B rows, 16B-aligned, stagger 16)
#define A_STAGE_B (BM * LDA * 2)      // 10240 B
#define B_STAGE_B (BK * LDB * 2)      // 12800 B
#define STAGE_B   (A_STAGE_B + B_STAGE_B)       // 23040
#define C_HALF_B  (64 * LDC * 4)                // 50176
#define DSM_BYTES (C_HALF_B)                    // 50176 >= 2*STAGE_B=46080

// ---------------- scratch (device globals; no allocations allowed) ----------
__device__ bf16  g_xbf[TOK * CDIM];
__device__ bf16  g_qkv[TOK * QKVN];        // window-ordered, bf16
__device__ bf16  g_attnout[TOK * CDIM];    // window-ordered, bf16
__device__ float g_x1[TOK * CDIM];         // fp32 residual spine
__device__ bf16  g_x1n[TOK * CDIM];
__device__ bf16  g_h[TOK * HID];
__device__ bf16  g_wqkv[CDIM * QKVN];
__device__ bf16  g_wproj[CDIM * CDIM];
__device__ bf16  g_w1[CDIM * HID];
__device__ bf16  g_w2[HID * CDIM];

// ---------------- helpers ----------------------------------------------------
__device__ __forceinline__ uint32_t smem_u32(const void* p) {
    uint32_t a;
    asm("{ .reg .u64 t; cvta.to.shared.u64 t, %1; cvt.u32.u64 %0, t; }" : "=r"(a) : "l"(p));
    return a;
}
#define CP_ASYNC16(dst, src) \
    asm volatile("cp.async.cg.shared.global [%0], [%1], 16;" :: "r"(dst), "l"(src))
#define CP_COMMIT() asm volatile("cp.async.commit_group;" ::: "memory")
#define CP_WAIT(n)  asm volatile("cp.async.wait_group %0;" :: "n"(n) : "memory")

__device__ __forceinline__ int map_win_to_global(int r) {
    int w = r >> 6, n = r & 63;
    int b = w >> 8, rem = w & 255;
    int wh = rem >> 4, ww = rem & 15;
    int i = n >> 3, j = n & 7;
    int h  = (wh * 8 + i + SS) & 127;
    int wc = (ww * 8 + j + SS) & 127;
    return (b << 14) + (h << 7) + wc;
}
__device__ __forceinline__ float gelu_exact(float v) {
    return 0.5f * v * (1.0f + erff(v * 0.70710678118654752440f));
}
__device__ __forceinline__ uint32_t pack_bf2(float a, float b) {
    __nv_bfloat162 h = __floats2bfloat162_rn(a, b);
    return *(uint32_t*)&h;
}

// ---------------- fp32 -> bf16 conversion -------------------------------------
__global__ void __launch_bounds__(256) conv_x_k(const float* __restrict__ src) {
    const size_t i = ((size_t)blockIdx.x * 256 + threadIdx.x) * 8;
    float4 v0 = *(const float4*)(src + i);
    float4 v1 = *(const float4*)(src + i + 4);
    uint4 o;
    o.x = pack_bf2(v0.x, v0.y); o.y = pack_bf2(v0.z, v0.w);
    o.z = pack_bf2(v1.x, v1.y); o.w = pack_bf2(v1.z, v1.w);
    *(uint4*)(g_xbf + i) = o;
}
#define S0 (CDIM*QKVN)
#define S1 (CDIM*CDIM)
#define S2 (CDIM*HID)
#define S3 (HID*CDIM)
__global__ void __launch_bounds__(256) conv_w_all(
    const float* __restrict__ w0, const float* __restrict__ w1,
    const float* __restrict__ w2, const float* __restrict__ w3)
{
    const int off = (blockIdx.x * 256 + threadIdx.x) * 8;
    const float* src; bf16* dst; int lo;
    if      (off < S0)            { src = w0; dst = g_wqkv;  lo = off; }
    else if (off < S0+S1)         { src = w1; dst = g_wproj; lo = off - S0; }
    else if (off < S0+S1+S2)      { src = w2; dst = g_w1;    lo = off - S0 - S1; }
    else if (off < S0+S1+S2+S3)   { src = w3; dst = g_w2;    lo = off - S0 - S1 - S2; }
    else return;
    float4 v0 = *(const float4*)(src + lo);
    float4 v1 = *(const float4*)(src + lo + 4);
    uint4 o;
    o.x = pack_bf2(v0.x, v0.y); o.y = pack_bf2(v0.z, v0.w);
    o.z = pack_bf2(v1.x, v1.y); o.w = pack_bf2(v1.z, v1.w);
    *(uint4*)(dst + lo) = o;
}

// ---------------- WMMA bf16 GEMM: 128x192 block, 8 warps, 64x48 warp tile -----
// MODE: 0=QKV(gather A; out bf16 g_qkv)
//       1=PROJ(scatter+resid -> fp32 g_x1, fused LayerNorm -> bf16 g_x1n)
//       2=FC1(gelu -> bf16 g_h)
//       3=FC2(+resid g_x1 -> fp32 Cout)
template<int KDIM, int NDIM, int MODE>
__global__ void __launch_bounds__(256) gemm_bf(
    const float* __restrict__ bias,
    const float* __restrict__ resid,
    float* __restrict__ Cout,
    const float* __restrict__ gamma,
    const float* __restrict__ beta)
{
    extern __shared__ __align__(16) unsigned char dsm[];
    bf16* sA[2] = { (bf16*)dsm, (bf16*)(dsm + STAGE_B) };
    bf16* sB[2] = { (bf16*)(dsm + A_STAGE_B), (bf16*)(dsm + STAGE_B + A_STAGE_B) };
    float* sC = (float*)dsm;   // 64x196 fp32 half-tile, aliases pipeline smem

    const int tid = threadIdx.x;
    const int bm = blockIdx.y * BM;
    const int bn = blockIdx.x * BN;

    const bf16* Aptr;
    const bf16* Bptr;
    if      constexpr (MODE == 0) { Aptr = g_xbf;     Bptr = g_wqkv; }
    else if constexpr (MODE == 1) { Aptr = g_attnout; Bptr = g_wproj; }
    else if constexpr (MODE == 2) { Aptr = g_x1n;     Bptr = g_w1; }
    else                          { Aptr = g_h;       Bptr = g_w2; }

    // A: 128 rows x 32 bf16; thread owns half-row (16 bf16 = 2 x 16B)
    const int aRow = tid >> 1, aHalf = tid & 1;
    int grA;
    if constexpr (MODE == 0) grA = map_win_to_global(bm + aRow);
    else                     grA = bm + aRow;
    const bf16* srcA = Aptr + (size_t)grA * KDIM + aHalf * 16;
    const uint32_t dAoff = (uint32_t)((aRow * LDA + aHalf * 16) * 2);
    const uint32_t dAb[2] = { smem_u32(sA[0]) + dAoff, smem_u32(sA[1]) + dAoff };

    // B: 32 rows x 192 bf16 = 768 x 8-elem chunks; 3 per thread
    int bRow[3], bCol[3];
    const bf16* srcB[3];
    uint32_t dBoff[3];
    #pragma unroll
    for (int l = 0; l < 3; l++) {
        int idx = tid + l * 256;               // 0..767
        bRow[l] = idx / 24; bCol[l] = (idx % 24) * 8;   // rows 0..31
        srcB[l] = Bptr + (size_t)bRow[l] * NDIM + bn + bCol[l];
        dBoff[l] = (uint32_t)((bRow[l] * LDB + bCol[l]) * 2);
    }
    const uint32_t dBb[2] = { smem_u32(sB[0]), smem_u32(sB[1]) };

    constexpr int T = KDIM / BK;
    const int wid = tid >> 5;
    const int wm = wid & 1, wn = wid >> 1;   // 2m x 4n, warp tile 64x48

    wmma::fragment<wmma::accumulator, 16, 16, 16, float> cf[4][3];
    #pragma unroll
    for (int i = 0; i < 4; i++)
        #pragma unroll
        for (int j = 0; j < 3; j++) wmma::fill_fragment(cf[i][j], 0.0f);

    // prefetch stage 0
    #pragma unroll
    for (int c = 0; c < 2; c++) CP_ASYNC16(dAb[0] + c * 16, srcA + c * 8);
    #pragma unroll
    for (int l = 0; l < 3; l++) CP_ASYNC16(dBb[0] + dBoff[l], srcB[l]);
    CP_COMMIT();

    for (int t = 0; t < T; t++) {
        if (t + 1 < T) {
            const int k0 = (t + 1) * BK;
            const int st = (t + 1) & 1;
            #pragma unroll
            for (int c = 0; c < 2; c++) CP_ASYNC16(dAb[st] + c * 16, srcA + k0 + c * 8);
            #pragma unroll
            for (int l = 0; l < 3; l++) CP_ASYNC16(dBb[st] + dBoff[l], srcB[l] + (size_t)k0 * NDIM);
            CP_COMMIT();
            CP_WAIT(1);
        } else {
            CP_WAIT(0);
        }
        __syncthreads();

        const bf16* At = sA[t & 1];
        const bf16* Bt = sB[t & 1];

        #pragma unroll
        for (int kk = 0; kk < BK; kk += 16) {
            wmma::fragment<wmma::matrix_a, 16, 16, 16, bf16, wmma::row_major> af[4];
            wmma::fragment<wmma::matrix_b, 16, 16, 16, bf16, wmma::row_major> bf_[3];
            #pragma unroll
            for (int i = 0; i < 4; i++)
                wmma::load_matrix_sync(af[i], At + (wm * 64 + i * 16) * LDA + kk, LDA);
            #pragma unroll
            for (int j = 0; j < 3; j++)
                wmma::load_matrix_sync(bf_[j], Bt + kk * LDB + wn * 48 + j * 16, LDB);
            #pragma unroll
            for (int i = 0; i < 4; i++)
                #pragma unroll
                for (int j = 0; j < 3; j++)
                    wmma::mma_sync(cf[i][j], af[i], bf_[j], cf[i][j]);
        }
        __syncthreads();
    }

    // ---------------- epilogue: two 64-row passes ------------------------------
    #pragma unroll
    for (int h = 0; h < 2; h++) {
        if (wm == h) {
            #pragma unroll
            for (int i = 0; i < 4; i++)
                #pragma unroll
                for (int j = 0; j < 3; j++)
                    wmma::store_matrix_sync(sC + (i * 16) * LDC + wn * 48 + j * 16,
                                            cf[i][j], LDC, wmma::mem_row_major);
        }
        __syncthreads();

        // 64 rows x 192 cols; thread owns (row = tid>>2, q = tid&3 -> 48 cols)
        const int row = tid >> 2;
        const int q   = tid & 3;
        const int c0  = q * 48;
        const int m   = bm + h * 64 + row;
        float v[48];
        #pragma unroll
        for (int c4 = 0; c4 < 12; c4++) {
            float4 w4 = *(const float4*)(sC + row * LDC + c0 + c4 * 4);
            const int gc = bn + c0 + c4 * 4;
            v[c4*4+0] = w4.x + __ldg(bias + gc + 0);
            v[c4*4+1] = w4.y + __ldg(bias + gc + 1);
            v[c4*4+2] = w4.z + __ldg(bias + gc + 2);
            v[c4*4+3] = w4.w + __ldg(bias + gc + 3);
        }

        if constexpr (MODE == 0) {
            bf16* dst = g_qkv + (size_t)m * QKVN + bn + c0;
            #pragma unroll
            for (int g = 0; g < 6; g++) {
                uint4 o;
                o.x = pack_bf2(v[g*8+0], v[g*8+1]); o.y = pack_bf2(v[g*8+2], v[g*8+3]);
                o.z = pack_bf2(v[g*8+4], v[g*8+5]); o.w = pack_bf2(v[g*8+6], v[g*8+7]);
                *(uint4*)(dst + g * 8) = o;
            }
        } else if constexpr (MODE == 1) {
            // proj + scatter + residual -> g_x1 ; fused LayerNorm -> g_x1n
            const int grow = map_win_to_global(m);
            const size_t o = (size_t)grow * CDIM + c0;   // bn == 0 (grid.x == 1)
            float s = 0.f, ss = 0.f;
            #pragma unroll
            for (int c4 = 0; c4 < 12; c4++) {
                float4 r = *(const float4*)(resid + o + c4 * 4);
                v[c4*4+0] += r.x; v[c4*4+1] += r.y; v[c4*4+2] += r.z; v[c4*4+3] += r.w;
                s  += v[c4*4+0] + v[c4*4+1] + v[c4*4+2] + v[c4*4+3];
                ss += v[c4*4+0]*v[c4*4+0] + v[c4*4+1]*v[c4*4+1]
                    + v[c4*4+2]*v[c4*4+2] + v[c4*4+3]*v[c4*4+3];
                *(float4*)(g_x1 + o + c4 * 4) =
                    make_float4(v[c4*4+0], v[c4*4+1], v[c4*4+2], v[c4*4+3]);
            }
            // full-row reduction across the 4 consecutive lanes sharing this row
            s  += __shfl_xor_sync(0xffffffffu, s, 1);
            ss += __shfl_xor_sync(0xffffffffu, ss, 1);
            s  += __shfl_xor_sync(0xffffffffu, s, 2);
            ss += __shfl_xor_sync(0xffffffffu, ss, 2);
            const float mu = s * (1.f / 192.f);
            const float var = ss * (1.f / 192.f) - mu * mu;
            const float rs = rsqrtf(var + 1e-5f);
            bf16* dst = g_x1n + o;
            #pragma unroll
            for (int g = 0; g < 6; g++) {
                const int gc = c0 + g * 8;
                float n0 = (v[g*8+0] - mu) * rs * __ldg(gamma + gc + 0) + __ldg(beta + gc + 0);
                float n1 = (v[g*8+1] - mu) * rs * __ldg(gamma + gc + 1) + __ldg(beta + gc + 1);
                float n2 = (v[g*8+2] - mu) * rs * __ldg(gamma + gc + 2) + __ldg(beta + gc + 2);
                float n3 = (v[g*8+3] - mu) * rs * __ldg(gamma + gc + 3) + __ldg(beta + gc + 3);
                float n4 = (v[g*8+4] - mu) * rs * __ldg(gamma + gc + 4) + __ldg(beta + gc + 4);
                float n5 = (v[g*8+5] - mu) * rs * __ldg(gamma + gc + 5) + __ldg(beta + gc + 5);
                float n6 = (v[g*8+6] - mu) * rs * __ldg(gamma + gc + 6) + __ldg(beta + gc + 6);
                float n7 = (v[g*8+7] - mu) * rs * __ldg(gamma + gc + 7) + __ldg(beta + gc + 7);
                uint4 ov;
                ov.x = pack_bf2(n0, n1); ov.y = pack_bf2(n2, n3);
                ov.z = pack_bf2(n4, n5); ov.w = pack_bf2(n6, n7);
                *(uint4*)(dst + g * 8) = ov;
            }
        } else if constexpr (MODE == 2) {
            bf16* dst = g_h + (size_t)m * HID + bn + c0;
            #pragma unroll
            for (int g = 0; g < 6; g++) {
                uint4 o;
                o.x = pack_bf2(gelu_exact(v[g*8+0]), gelu_exact(v[g*8+1]));
                o.y = pack_bf2(gelu_exact(v[g*8+2]), gelu_exact(v[g*8+3]));
                o.z = pack_bf2(gelu_exact(v[g*8+4]), gelu_exact(v[g*8+5]));
                o.w = pack_bf2(gelu_exact(v[g*8+6]), gelu_exact(v[g*8+7]));
                *(uint4*)(dst + g * 8) = o;
            }
        } else {
            const size_t o = (size_t)m * CDIM + c0;      // bn == 0 (grid.x == 1)
            #pragma unroll
            for (int c4 = 0; c4 < 12; c4++) {
                float4 r = *(const float4*)(g_x1 + o + c4 * 4);
                *(float4*)(Cout + o + c4 * 4) =
                    make_float4(v[c4*4+0] + r.x, v[c4*4+1] + r.y, v[c4*4+2] + r.z, v[c4*4+3] + r.w);
            }
        }
        __syncthreads();
    }
}

// ---------------- attention: WMMA tensor-core (proven, round 7) ---------------
#define ALQ 40
#define ALS 68
#define ALP 72
#define OFF_K 0
#define OFF_V 5120
#define OFF_Q 10240
#define OFF_S 15360
#define OFF_P 32768
#define ATT_SMEM (32768 + 64 * ALP * 2)

__global__ void __launch_bounds__(128) attn_tc(const float* __restrict__ rpb)
{
    const int w = blockIdx.x, head = blockIdx.y;
    const int tid = threadIdx.x;
    const int wid = tid >> 5;

    __shared__ __align__(16) unsigned char buf[ATT_SMEM];
    bf16*  sK = (bf16*)(buf + OFF_K);
    bf16*  sV = (bf16*)(buf + OFF_V);
    bf16*  sQ = (bf16*)(buf + OFF_Q);
    float* sS = (float*)(buf + OFF_S);
    bf16*  sP = (bf16*)(buf + OFF_P);
    __shared__ float sRp[225];
    __shared__ int   sReg[64];

    const bf16* base = g_qkv + (size_t)w * 64 * QKVN + head * 32;
    #pragma unroll
    for (int l = 0; l < 2; l++) {
        int i = tid + l * 128;
        int row = i >> 2, cg = (i & 3) * 8;
        const bf16* src = base + (size_t)row * QKVN;
        *(uint4*)(sQ + row * ALQ + cg) = *(const uint4*)(src + cg);
        *(uint4*)(sK + row * ALQ + cg) = *(const uint4*)(src + CDIM + cg);
        *(uint4*)(sV + row * ALQ + cg) = *(const uint4*)(src + 2 * CDIM + cg);
    }
    for (int i = tid; i < 225; i += 128) sRp[i] = rpb[i * NHEAD + head];
    if (tid < 64) {
        int rem = w & 255; int wh = rem >> 4, ww = rem & 15;
        int hs  = wh * 8 + (tid >> 3);
        int wsc = ww * 8 + (tid & 7);
        int rh = hs  < 120 ? 0 : (hs  < 124 ? 1 : 2);
        int rw = wsc < 120 ? 0 : (wsc < 124 ? 1 : 2);
        sReg[tid] = rh * 3 + rw;
    }
    __syncthreads();

    {
        wmma::fragment<wmma::matrix_a, 16, 16, 16, bf16, wmma::row_major> aq[2];
        wmma::load_matrix_sync(aq[0], sQ + wid * 16 * ALQ + 0,  ALQ);
        wmma::load_matrix_sync(aq[1], sQ + wid * 16 * ALQ + 16, ALQ);
        #pragma unroll
        for (int n = 0; n < 4; n++) {
            wmma::fragment<wmma::accumulator, 16, 16, 16, float> s;
            wmma::fill_fragment(s, 0.0f);
            #pragma unroll
            for (int k = 0; k < 2; k++) {
                wmma::fragment<wmma::matrix_b, 16, 16, 16, bf16, wmma::col_major> bk;
                wmma::load_matrix_sync(bk, sK + n * 16 * ALQ + k * 16, ALQ);
                wmma::mma_sync(s, aq[k], bk, s);
            }
            wmma::store_matrix_sync(sS + wid * 16 * ALS + n * 16, s, ALS, wmma::mem_row_major);
        }
    }
    __syncthreads();

    {
        const int row = tid >> 1, half = tid & 1;
        const int i1 = row >> 3, j1 = row & 7;
        const int regr = sReg[row];
        const float scale = 0.17677669529663689f;
        float e[32];
        float sum = 0.f;
        #pragma unroll
        for (int c = 0; c < 32; c++) {
            const int col = half * 32 + c;
            const int i2 = col >> 3, j2 = col & 7;
            const float b = sRp[(i1 - i2 + 7) * 15 + (j1 - j2 + 7)];
            const float msk = (sReg[col] == regr) ? 0.f : -100.f;
            const float ev = __expf(sS[row * ALS + col] * scale + b + msk);
            e[c] = ev; sum += ev;
        }
        sum += __shfl_xor_sync(0xffffffffu, sum, 1);
        const float inv = 1.f / sum;
        #pragma unroll
        for (int c = 0; c < 32; c += 2)
            *(uint32_t*)(sP + row * ALP + half * 32 + c) = pack_bf2(e[c] * inv, e[c+1] * inv);
    }
    __syncthreads();

    {
        wmma::fragment<wmma::matrix_a, 16, 16, 16, bf16, wmma::row_major> ap[4];
        #pragma unroll
        for (int k = 0; k < 4; k++)
            wmma::load_matrix_sync(ap[k], sP + wid * 16 * ALP + k * 16, ALP);
        #pragma unroll
        for (int d = 0; d < 2; d++) {
            wmma::fragment<wmma::accumulator, 16, 16, 16, float> o;
            wmma::fill_fragment(o, 0.0f);
            #pragma unroll
            for (int k = 0; k < 4; k++) {
                wmma::fragment<wmma::matrix_b, 16, 16, 16, bf16, wmma::row_major> bv;
                wmma::load_matrix_sync(bv, sV + k * 16 * ALQ + d * 16, ALQ);
                wmma::mma_sync(o, ap[k], bv, o);
            }
            wmma::store_matrix_sync(sS + wid * 16 * 36 + d * 16, o, 36, wmma::mem_row_major);
        }
    }
    __syncthreads();

    {
        const int row = tid >> 1, half = tid & 1;
        const float* src = sS + row * 36 + half * 16;
        float4 f0 = *(const float4*)(src + 0);
        float4 f1 = *(const float4*)(src + 4);
        float4 f2 = *(const float4*)(src + 8);
        float4 f3 = *(const float4*)(src + 12);
        bf16* op = g_attnout + ((size_t)(w * 64 + row)) * CDIM + head * 32 + half * 16;
        *(uint2*)(op + 0)  = make_uint2(pack_bf2(f0.x, f0.y), pack_bf2(f0.z, f0.w));
        *(uint2*)(op + 4)  = make_uint2(pack_bf2(f1.x, f1.y), pack_bf2(f1.z, f1.w));
        *(uint2*)(op + 8)  = make_uint2(pack_bf2(f2.x, f2.y), pack_bf2(f2.z, f2.w));
        *(uint2*)(op + 12) = make_uint2(pack_bf2(f3.x, f3.y), pack_bf2(f3.z, f3.w));
    }
}

// ---------------- launch -----------------------------------------------------
extern "C" void kernel_launch(void* const* d_in, const int* in_sizes, int n_in,
                              void* d_out, int out_size)
{
    const float* x       = (const float*)d_in[0];
    const float* qkv_w   = (const float*)d_in[1];
    const float* qkv_b   = (const float*)d_in[2];
    const float* proj_w  = (const float*)d_in[3];
    const float* proj_b  = (const float*)d_in[4];
    const float* rpb     = (const float*)d_in[5];
    const float* norm2_g = (const float*)d_in[6];
    const float* norm2_b = (const float*)d_in[7];
    const float* mlp_w1  = (const float*)d_in[8];
    const float* mlp_b1  = (const float*)d_in[9];
    const float* mlp_w2  = (const float*)d_in[10];
    const float* mlp_b2  = (const float*)d_in[11];
    float* out = (float*)d_out;

    cudaFuncSetAttribute(gemm_bf<192, 576, 0>, cudaFuncAttributeMaxDynamicSharedMemorySize, DSM_BYTES);
    cudaFuncSetAttribute(gemm_bf<192, 192, 1>, cudaFuncAttributeMaxDynamicSharedMemorySize, DSM_BYTES);
    cudaFuncSetAttribute(gemm_bf<192, 768, 2>, cudaFuncAttributeMaxDynamicSharedMemorySize, DSM_BYTES);
    cudaFuncSetAttribute(gemm_bf<768, 192, 3>, cudaFuncAttributeMaxDynamicSharedMemorySize, DSM_BYTES);

    // precision conversions
    conv_x_k<<<TOK * CDIM / (256 * 8), 256>>>(x);
    conv_w_all<<<(S0 + S1 + S2 + S3) / (256 * 8), 256>>>(qkv_w, proj_w, mlp_w1, mlp_w2);

    // 1) QKV = gather(x) @ qkv_w + b  -> bf16 g_qkv (window order)
    gemm_bf<192, 576, 0><<<dim3(3, 1024), 256, DSM_BYTES>>>(qkv_b, nullptr, nullptr, nullptr, nullptr);
    // 2) windowed attention (tensor cores) -> bf16 g_attnout
    attn_tc<<<dim3(NWIN, NHEAD), 128>>>(rpb);
    // 3) proj + scatter + residual + fused LayerNorm -> g_x1 (fp32), g_x1n (bf16)
    gemm_bf<192, 192, 1><<<dim3(1, 1024), 256, DSM_BYTES>>>(proj_b, x, nullptr, norm2_g, norm2_b);
    // 4) fc1 + GELU -> bf16 g_h
    gemm_bf<192, 768, 2><<<dim3(4, 1024), 256, DSM_BYTES>>>(mlp_b1, nullptr, nullptr, nullptr, nullptr);
    // 5) fc2 + residual -> fp32 out
    gemm_bf<768, 192, 3><<<dim3(1, 1024), 256, DSM_BYTES>>>(mlp_b2, nullptr, out, nullptr, nullptr);
}

// round 11
// speedup vs baseline: 1.0666x; 1.0666x over previous
#include <cuda_runtime.h>
#include <cuda_bf16.h>
#include <mma.h>
#include <cstdint>
#include <math.h>

using namespace nvcuda;
typedef __nv_bfloat16 bf16;

// Problem constants (fixed shapes)
#define TOK   131072      // B*H*W = 8*128*128
#define CDIM  192
#define HID   768
#define QKVN  576
#define NHEAD 6
#define SS    4
#define NWIN  2048        // B * 16 * 16

// GEMM tiling: block 128x96, 4 warps (2m x 2n), warp tile 64x48  (R9 proven)
#define BM 128
#define BN 96
#define BK 32
#define LDA 40            // bf16 ld, 80B rows
#define LDB 104           // bf16 ld for B (96+8)
#define LDC 100           // fp32 ld for C half-tile
#define A_STAGE_B (BM * LDA * 2)      // 10240 B
#define B_STAGE_B (BK * LDB * 2)      // 6656 B
#define STAGE_B   (A_STAGE_B + B_STAGE_B)
#define SMEM_BYTES (2 * STAGE_B)      // 33792; C half-tile 64*100*4=25600 fits

// ---------------- scratch (device globals; no allocations allowed) ----------
__device__ bf16  g_xbf[TOK * CDIM];
__device__ bf16  g_qkv[TOK * QKVN];        // window-ordered, bf16
__device__ bf16  g_attnout[TOK * CDIM];    // window-ordered, bf16
__device__ float g_x1[TOK * CDIM];         // fp32 residual spine
__device__ bf16  g_x1n[TOK * CDIM];
__device__ bf16  g_h[TOK * HID];
__device__ bf16  g_wqkv[CDIM * QKVN];
__device__ bf16  g_wproj[CDIM * CDIM];
__device__ bf16  g_w1[CDIM * HID];
__device__ bf16  g_w2[HID * CDIM];

// ---------------- helpers ----------------------------------------------------
__device__ __forceinline__ uint32_t smem_u32(const void* p) {
    uint32_t a;
    asm("{ .reg .u64 t; cvta.to.shared.u64 t, %1; cvt.u32.u64 %0, t; }" : "=r"(a) : "l"(p));
    return a;
}
#define CP_ASYNC16(dst, src) \
    asm volatile("cp.async.cg.shared.global [%0], [%1], 16;" :: "r"(dst), "l"(src))
#define CP_COMMIT() asm volatile("cp.async.commit_group;" ::: "memory")
#define CP_WAIT(n)  asm volatile("cp.async.wait_group %0;" :: "n"(n) : "memory")

__device__ __forceinline__ int map_win_to_global(int r) {
    int w = r >> 6, n = r & 63;
    int b = w >> 8, rem = w & 255;
    int wh = rem >> 4, ww = rem & 15;
    int i = n >> 3, j = n & 7;
    int h  = (wh * 8 + i + SS) & 127;
    int wc = (ww * 8 + j + SS) & 127;
    return (b << 14) + (h << 7) + wc;
}
__device__ __forceinline__ float gelu_exact(float v) {
    return 0.5f * v * (1.0f + erff(v * 0.70710678118654752440f));
}
__device__ __forceinline__ uint32_t pack_bf2(float a, float b) {
    __nv_bfloat162 h = __floats2bfloat162_rn(a, b);
    return *(uint32_t*)&h;
}

// ---------------- fp32 -> bf16 conversion -------------------------------------
__global__ void __launch_bounds__(256) conv_x_k(const float* __restrict__ src) {
    const size_t i = ((size_t)blockIdx.x * 256 + threadIdx.x) * 8;
    float4 v0 = *(const float4*)(src + i);
    float4 v1 = *(const float4*)(src + i + 4);
    uint4 o;
    o.x = pack_bf2(v0.x, v0.y); o.y = pack_bf2(v0.z, v0.w);
    o.z = pack_bf2(v1.x, v1.y); o.w = pack_bf2(v1.z, v1.w);
    *(uint4*)(g_xbf + i) = o;
}
#define S0 (CDIM*QKVN)
#define S1 (CDIM*CDIM)
#define S2 (CDIM*HID)
#define S3 (HID*CDIM)
__global__ void __launch_bounds__(256) conv_w_all(
    const float* __restrict__ w0, const float* __restrict__ w1,
    const float* __restrict__ w2, const float* __restrict__ w3)
{
    const int off = (blockIdx.x * 256 + threadIdx.x) * 8;
    const float* src; bf16* dst; int lo;
    if      (off < S0)            { src = w0; dst = g_wqkv;  lo = off; }
    else if (off < S0+S1)         { src = w1; dst = g_wproj; lo = off - S0; }
    else if (off < S0+S1+S2)      { src = w2; dst = g_w1;    lo = off - S0 - S1; }
    else if (off < S0+S1+S2+S3)   { src = w3; dst = g_w2;    lo = off - S0 - S1 - S2; }
    else return;
    float4 v0 = *(const float4*)(src + lo);
    float4 v1 = *(const float4*)(src + lo + 4);
    uint4 o;
    o.x = pack_bf2(v0.x, v0.y); o.y = pack_bf2(v0.z, v0.w);
    o.z = pack_bf2(v1.x, v1.y); o.w = pack_bf2(v1.z, v1.w);
    *(uint4*)(dst + lo) = o;
}

// ---------------- WMMA bf16 GEMM: 128x96 block, 64x48 warp tile (R9) ----------
// MODE: 0=QKV(gather A; out bf16 g_qkv)  1=PROJ(scatter+resid -> fp32 g_x1)
//       2=FC1(gelu -> bf16 g_h)          3=FC2(+resid g_x1 -> fp32 Cout)
template<int KDIM, int NDIM, int MODE>
__global__ void __launch_bounds__(128) gemm_bf(
    const float* __restrict__ bias,
    const float* __restrict__ resid,
    float* __restrict__ Cout)
{
    __shared__ __align__(16) unsigned char smem[SMEM_BYTES];
    bf16* sA[2] = { (bf16*)smem, (bf16*)(smem + STAGE_B) };
    bf16* sB[2] = { (bf16*)(smem + A_STAGE_B), (bf16*)(smem + STAGE_B + A_STAGE_B) };
    float* sC = (float*)smem;   // 64x100 fp32 half-tile, aliases pipeline smem

    const int tid = threadIdx.x;
    const int bm = blockIdx.y * BM;
    const int bn = blockIdx.x * BN;

    const bf16* Aptr;
    const bf16* Bptr;
    if      constexpr (MODE == 0) { Aptr = g_xbf;     Bptr = g_wqkv; }
    else if constexpr (MODE == 1) { Aptr = g_attnout; Bptr = g_wproj; }
    else if constexpr (MODE == 2) { Aptr = g_x1n;     Bptr = g_w1; }
    else                          { Aptr = g_h;       Bptr = g_w2; }

    // A: thread owns row tid (32 bf16 = 4 x 16B)
    int grA;
    if constexpr (MODE == 0) grA = map_win_to_global(bm + tid);
    else                     grA = bm + tid;
    const bf16* srcA = Aptr + (size_t)grA * KDIM;
    const uint32_t dA0 = smem_u32(sA[0]) + (uint32_t)(tid * LDA * 2);
    const uint32_t dA1 = smem_u32(sA[1]) + (uint32_t)(tid * LDA * 2);

    // B: 32 rows x 96 bf16 = 384 x 8-elem chunks; 3 per thread
    int bRow[3], bCol[3];
    const bf16* srcB[3];
    uint32_t dBoff[3];
    #pragma unroll
    for (int l = 0; l < 3; l++) {
        int idx = tid + l * 128;               // 0..383
        bRow[l] = idx / 12; bCol[l] = (idx % 12) * 8;   // rows 0..31
        srcB[l] = Bptr + (size_t)bRow[l] * NDIM + bn + bCol[l];
        dBoff[l] = (uint32_t)((bRow[l] * LDB + bCol[l]) * 2);
    }
    const uint32_t dBb[2] = { smem_u32(sB[0]), smem_u32(sB[1]) };

    constexpr int T = KDIM / BK;
    const int wid = tid >> 5;
    const int wm = wid & 1, wn = wid >> 1;   // warp tile 64x48

    wmma::fragment<wmma::accumulator, 16, 16, 16, float> cf[4][3];
    #pragma unroll
    for (int i = 0; i < 4; i++)
        #pragma unroll
        for (int j = 0; j < 3; j++) wmma::fill_fragment(cf[i][j], 0.0f);

    // prefetch stage 0
    #pragma unroll
    for (int c = 0; c < 4; c++) CP_ASYNC16(dA0 + c * 16, srcA + c * 8);
    #pragma unroll
    for (int l = 0; l < 3; l++) CP_ASYNC16(dBb[0] + dBoff[l], srcB[l]);
    CP_COMMIT();

    for (int t = 0; t < T; t++) {
        if (t + 1 < T) {
            const int k0 = (t + 1) * BK;
            const uint32_t dAx = ((t + 1) & 1) ? dA1 : dA0;
            const uint32_t dBx = dBb[(t + 1) & 1];
            #pragma unroll
            for (int c = 0; c < 4; c++) CP_ASYNC16(dAx + c * 16, srcA + k0 + c * 8);
            #pragma unroll
            for (int l = 0; l < 3; l++) CP_ASYNC16(dBx + dBoff[l], srcB[l] + (size_t)k0 * NDIM);
            CP_COMMIT();
            CP_WAIT(1);
        } else {
            CP_WAIT(0);
        }
        __syncthreads();

        const bf16* At = sA[t & 1];
        const bf16* Bt = sB[t & 1];

        #pragma unroll
        for (int kk = 0; kk < BK; kk += 16) {
            wmma::fragment<wmma::matrix_a, 16, 16, 16, bf16, wmma::row_major> af[4];
            wmma::fragment<wmma::matrix_b, 16, 16, 16, bf16, wmma::row_major> bf_[3];
            #pragma unroll
            for (int i = 0; i < 4; i++)
                wmma::load_matrix_sync(af[i], At + (wm * 64 + i * 16) * LDA + kk, LDA);
            #pragma unroll
            for (int j = 0; j < 3; j++)
                wmma::load_matrix_sync(bf_[j], Bt + kk * LDB + wn * 48 + j * 16, LDB);
            #pragma unroll
            for (int i = 0; i < 4; i++)
                #pragma unroll
                for (int j = 0; j < 3; j++)
                    wmma::mma_sync(cf[i][j], af[i], bf_[j], cf[i][j]);
        }
        __syncthreads();
    }

    // ---------------- epilogue: two 64-row passes ------------------------------
    #pragma unroll
    for (int h = 0; h < 2; h++) {
        if (wm == h) {
            #pragma unroll
            for (int i = 0; i < 4; i++)
                #pragma unroll
                for (int j = 0; j < 3; j++)
                    wmma::store_matrix_sync(sC + (i * 16) * LDC + wn * 48 + j * 16,
                                            cf[i][j], LDC, wmma::mem_row_major);
        }
        __syncthreads();

        // 64 rows x 96 cols; thread owns (row = tid>>1, half = tid&1 -> 48 cols)
        const int row  = tid >> 1;
        const int half = tid & 1;
        const int c0   = half * 48;
        const int m    = bm + h * 64 + row;
        float v[48];
        #pragma unroll
        for (int c4 = 0; c4 < 12; c4++) {
            float4 w4 = *(const float4*)(sC + row * LDC + c0 + c4 * 4);
            const int gc = bn + c0 + c4 * 4;
            v[c4*4+0] = w4.x + __ldg(bias + gc + 0);
            v[c4*4+1] = w4.y + __ldg(bias + gc + 1);
            v[c4*4+2] = w4.z + __ldg(bias + gc + 2);
            v[c4*4+3] = w4.w + __ldg(bias + gc + 3);
        }

        if constexpr (MODE == 0) {
            bf16* dst = g_qkv + (size_t)m * QKVN + bn + c0;
            #pragma unroll
            for (int g = 0; g < 6; g++) {
                uint4 o;
                o.x = pack_bf2(v[g*8+0], v[g*8+1]); o.y = pack_bf2(v[g*8+2], v[g*8+3]);
                o.z = pack_bf2(v[g*8+4], v[g*8+5]); o.w = pack_bf2(v[g*8+6], v[g*8+7]);
                *(uint4*)(dst + g * 8) = o;
            }
        } else if constexpr (MODE == 1) {
            const int grow = map_win_to_global(m);
            const size_t o = (size_t)grow * CDIM + bn + c0;
            #pragma unroll
            for (int c4 = 0; c4 < 12; c4++) {
                float4 r = *(const float4*)(resid + o + c4 * 4);
                *(float4*)(g_x1 + o + c4 * 4) =
                    make_float4(v[c4*4+0] + r.x, v[c4*4+1] + r.y, v[c4*4+2] + r.z, v[c4*4+3] + r.w);
            }
        } else if constexpr (MODE == 2) {
            bf16* dst = g_h + (size_t)m * HID + bn + c0;
            #pragma unroll
            for (int g = 0; g < 6; g++) {
                uint4 o;
                o.x = pack_bf2(gelu_exact(v[g*8+0]), gelu_exact(v[g*8+1]));
                o.y = pack_bf2(gelu_exact(v[g*8+2]), gelu_exact(v[g*8+3]));
                o.z = pack_bf2(gelu_exact(v[g*8+4]), gelu_exact(v[g*8+5]));
                o.w = pack_bf2(gelu_exact(v[g*8+6]), gelu_exact(v[g*8+7]));
                *(uint4*)(dst + g * 8) = o;
            }
        } else {
            const size_t o = (size_t)m * CDIM + bn + c0;
            #pragma unroll
            for (int c4 = 0; c4 < 12; c4++) {
                float4 r = *(const float4*)(g_x1 + o + c4 * 4);
                *(float4*)(Cout + o + c4 * 4) =
                    make_float4(v[c4*4+0] + r.x, v[c4*4+1] + r.y, v[c4*4+2] + r.z, v[c4*4+3] + r.w);
            }
        }
        __syncthreads();
    }
}

// ---------------- LayerNorm: one warp per token, bf16 out ---------------------
__global__ void __launch_bounds__(256) ln_norm_k(const float* __restrict__ gamma,
                                                 const float* __restrict__ beta)
{
    const int r = blockIdx.x * 8 + (threadIdx.x >> 5);
    const int lane = threadIdx.x & 31;
    const float* p = g_x1 + (size_t)r * CDIM;
    float v[6];
    float s = 0.f, ss = 0.f;
    #pragma unroll
    for (int k = 0; k < 6; k++) {
        v[k] = p[lane + k * 32];
        s += v[k]; ss += v[k] * v[k];
    }
    #pragma unroll
    for (int o = 16; o; o >>= 1) {
        s  += __shfl_xor_sync(0xffffffffu, s,  o);
        ss += __shfl_xor_sync(0xffffffffu, ss, o);
    }
    const float mu = s * (1.f / 192.f);
    const float var = ss * (1.f / 192.f) - mu * mu;
    const float rs = rsqrtf(var + 1e-5f);
    bf16* q = g_x1n + (size_t)r * CDIM;
    #pragma unroll
    for (int k = 0; k < 6; k++) {
        const int c = lane + k * 32;
        q[c] = __float2bfloat16_rn((v[k] - mu) * rs * __ldg(gamma + c) + __ldg(beta + c));
    }
}

// ---------------- attention: WMMA, smem-aliased layout ------------------------
// V@0, Q@5120, K@10240, S@15360; P aliases Q+K (dead after S GEMM) at 5120.
// Static smem 32768+~1.2K -> 6 CTAs/SM (was 5 at 43KB).
#define ALQ 40
#define ALS 68
#define ALP 72
#define OFF_V 0
#define OFF_Q 5120
#define OFF_K 10240
#define OFF_S 15360
#define OFF_P 5120
#define ATT_SMEM (15360 + 64 * ALS * 4)   // 32768

__global__ void __launch_bounds__(128) attn_tc(const float* __restrict__ rpb)
{
    const int w = blockIdx.x, head = blockIdx.y;
    const int tid = threadIdx.x;
    const int wid = tid >> 5;

    __shared__ __align__(16) unsigned char buf[ATT_SMEM];
    bf16*  sV = (bf16*)(buf + OFF_V);
    bf16*  sQ = (bf16*)(buf + OFF_Q);
    bf16*  sK = (bf16*)(buf + OFF_K);
    float* sS = (float*)(buf + OFF_S);
    bf16*  sP = (bf16*)(buf + OFF_P);   // aliases Q+K after S GEMM
    __shared__ float sRp[225];
    __shared__ int   sReg[64];

    const bf16* base = g_qkv + (size_t)w * 64 * QKVN + head * 32;
    #pragma unroll
    for (int l = 0; l < 2; l++) {
        int i = tid + l * 128;
        int row = i >> 2, cg = (i & 3) * 8;
        const bf16* src = base + (size_t)row * QKVN;
        *(uint4*)(sQ + row * ALQ + cg) = *(const uint4*)(src + cg);
        *(uint4*)(sK + row * ALQ + cg) = *(const uint4*)(src + CDIM + cg);
        *(uint4*)(sV + row * ALQ + cg) = *(const uint4*)(src + 2 * CDIM + cg);
    }
    for (int i = tid; i < 225; i += 128) sRp[i] = rpb[i * NHEAD + head];
    if (tid < 64) {
        int rem = w & 255; int wh = rem >> 4, ww = rem & 15;
        int hs  = wh * 8 + (tid >> 3);
        int wsc = ww * 8 + (tid & 7);
        int rh = hs  < 120 ? 0 : (hs  < 124 ? 1 : 2);
        int rw = wsc < 120 ? 0 : (wsc < 124 ? 1 : 2);
        sReg[tid] = rh * 3 + rw;
    }
    __syncthreads();

    // ---- S = Q @ K^T
    {
        wmma::fragment<wmma::matrix_a, 16, 16, 16, bf16, wmma::row_major> aq[2];
        wmma::load_matrix_sync(aq[0], sQ + wid * 16 * ALQ + 0,  ALQ);
        wmma::load_matrix_sync(aq[1], sQ + wid * 16 * ALQ + 16, ALQ);
        #pragma unroll
        for (int n = 0; n < 4; n++) {
            wmma::fragment<wmma::accumulator, 16, 16, 16, float> s;
            wmma::fill_fragment(s, 0.0f);
            #pragma unroll
            for (int k = 0; k < 2; k++) {
                wmma::fragment<wmma::matrix_b, 16, 16, 16, bf16, wmma::col_major> bk;
                wmma::load_matrix_sync(bk, sK + n * 16 * ALQ + k * 16, ALQ);
                wmma::mma_sync(s, aq[k], bk, s);
            }
            wmma::store_matrix_sync(sS + wid * 16 * ALS + n * 16, s, ALS, wmma::mem_row_major);
        }
    }
    __syncthreads();   // S done; Q,K now dead -> P may overwrite

    // ---- softmax: 2 threads per row; fold 1/sum into P
    {
        const int row = tid >> 1, half = tid & 1;
        const int i1 = row >> 3, j1 = row & 7;
        const int regr = sReg[row];
        const float scale = 0.17677669529663689f;
        float e[32];
        float sum = 0.f;
        #pragma unroll
        for (int c = 0; c < 32; c++) {
            const int col = half * 32 + c;
            const int i2 = col >> 3, j2 = col & 7;
            const float b = sRp[(i1 - i2 + 7) * 15 + (j1 - j2 + 7)];
            const float msk = (sReg[col] == regr) ? 0.f : -100.f;
            const float ev = __expf(sS[row * ALS + col] * scale + b + msk);
            e[c] = ev; sum += ev;
        }
        sum += __shfl_xor_sync(0xffffffffu, sum, 1);
        const float inv = 1.f / sum;
        #pragma unroll
        for (int c = 0; c < 32; c += 2)
            *(uint32_t*)(sP + row * ALP + half * 32 + c) = pack_bf2(e[c] * inv, e[c+1] * inv);
    }
    __syncthreads();

    // ---- O = P @ V -> stage in sS (ld 36)
    {
        wmma::fragment<wmma::matrix_a, 16, 16, 16, bf16, wmma::row_major> ap[4];
        #pragma unroll
        for (int k = 0; k < 4; k++)
            wmma::load_matrix_sync(ap[k], sP + wid * 16 * ALP + k * 16, ALP);
        #pragma unroll
        for (int d = 0; d < 2; d++) {
            wmma::fragment<wmma::accumulator, 16, 16, 16, float> o;
            wmma::fill_fragment(o, 0.0f);
            #pragma unroll
            for (int k = 0; k < 4; k++) {
                wmma::fragment<wmma::matrix_b, 16, 16, 16, bf16, wmma::row_major> bv;
                wmma::load_matrix_sync(bv, sV + k * 16 * ALQ + d * 16, ALQ);
                wmma::mma_sync(o, ap[k], bv, o);
            }
            wmma::store_matrix_sync(sS + wid * 16 * 36 + d * 16, o, 36, wmma::mem_row_major);
        }
    }
    __syncthreads();

    // ---- write out
    {
        const int row = tid >> 1, half = tid & 1;
        const float* src = sS + row * 36 + half * 16;
        float4 f0 = *(const float4*)(src + 0);
        float4 f1 = *(const float4*)(src + 4);
        float4 f2 = *(const float4*)(src + 8);
        float4 f3 = *(const float4*)(src + 12);
        bf16* op = g_attnout + ((size_t)(w * 64 + row)) * CDIM + head * 32 + half * 16;
        *(uint2*)(op + 0)  = make_uint2(pack_bf2(f0.x, f0.y), pack_bf2(f0.z, f0.w));
        *(uint2*)(op + 4)  = make_uint2(pack_bf2(f1.x, f1.y), pack_bf2(f1.z, f1.w));
        *(uint2*)(op + 8)  = make_uint2(pack_bf2(f2.x, f2.y), pack_bf2(f2.z, f2.w));
        *(uint2*)(op + 12) = make_uint2(pack_bf2(f3.x, f3.y), pack_bf2(f3.z, f3.w));
    }
}

// ---------------- launch -----------------------------------------------------
extern "C" void kernel_launch(void* const* d_in, const int* in_sizes, int n_in,
                              void* d_out, int out_size)
{
    const float* x       = (const float*)d_in[0];
    const float* qkv_w   = (const float*)d_in[1];
    const float* qkv_b   = (const float*)d_in[2];
    const float* proj_w  = (const float*)d_in[3];
    const float* proj_b  = (const float*)d_in[4];
    const float* rpb     = (const float*)d_in[5];
    const float* norm2_g = (const float*)d_in[6];
    const float* norm2_b = (const float*)d_in[7];
    const float* mlp_w1  = (const float*)d_in[8];
    const float* mlp_b1  = (const float*)d_in[9];
    const float* mlp_w2  = (const float*)d_in[10];
    const float* mlp_b2  = (const float*)d_in[11];
    float* out = (float*)d_out;

    // precision conversions
    conv_x_k<<<TOK * CDIM / (256 * 8), 256>>>(x);
    conv_w_all<<<(S0 + S1 + S2 + S3) / (256 * 8), 256>>>(qkv_w, proj_w, mlp_w1, mlp_w2);

    // 1) QKV = gather(x) @ qkv_w + b  -> bf16 g_qkv (window order)
    gemm_bf<192, 576, 0><<<dim3(6, 1024), 128>>>(qkv_b, nullptr, nullptr);
    // 2) windowed attention (tensor cores) -> bf16 g_attnout
    attn_tc<<<dim3(NWIN, NHEAD), 128>>>(rpb);
    // 3) proj + scatter + residual -> fp32 g_x1
    gemm_bf<192, 192, 1><<<dim3(2, 1024), 128>>>(proj_b, x, nullptr);
    // 4) LayerNorm(g_x1) -> bf16 g_x1n
    ln_norm_k<<<TOK / 8, 256>>>(norm2_g, norm2_b);
    // 5) fc1 + GELU -> bf16 g_h
    gemm_bf<192, 768, 2><<<dim3(8, 1024), 128>>>(mlp_b1, nullptr, nullptr);
    // 6) fc2 + residual -> fp32 out
    gemm_bf<768, 192, 3><<<dim3(2, 1024), 128>>>(mlp_b2, nullptr, out);
}

// round 12
// speedup vs baseline: 1.1326x; 1.0619x over previous
#include <cuda_runtime.h>
#include <cuda_bf16.h>
#include <mma.h>
#include <cstdint>
#include <math.h>

using namespace nvcuda;
typedef __nv_bfloat16 bf16;

// Problem constants (fixed shapes)
#define TOK   131072      // B*H*W = 8*128*128
#define CDIM  192
#define HID   768
#define QKVN  576
#define NHEAD 6
#define SS    4
#define NWIN  2048        // B * 16 * 16

// GEMM tiling: block 128x96, 4 warps (2m x 2n), warp tile 64x48  (R9 proven)
#define BM 128
#define BN 96
#define BK 32
#define LDA 40            // bf16 ld, 80B rows
#define LDB 104           // bf16 ld for B (96+8)
#define LDC 100           // fp32 ld for C half-tile
#define A_STAGE_B (BM * LDA * 2)      // 10240 B
#define B_STAGE_B (BK * LDB * 2)      // 6656 B
#define STAGE_B   (A_STAGE_B + B_STAGE_B)
#define SMEM_BYTES (2 * STAGE_B)      // 33792; C half-tile 64*100*4=25600 fits

// ---------------- scratch (device globals; no allocations allowed) ----------
__device__ bf16  g_xbf[TOK * CDIM];
__device__ bf16  g_qkv[TOK * QKVN];        // window-ordered, bf16
__device__ bf16  g_attnout[TOK * CDIM];    // window-ordered, bf16
__device__ float g_x1[TOK * CDIM];         // fp32 residual spine
__device__ bf16  g_x1n[TOK * CDIM];
__device__ bf16  g_h[TOK * HID];
__device__ bf16  g_wqkv[CDIM * QKVN];
__device__ bf16  g_wproj[CDIM * CDIM];
__device__ bf16  g_w1[CDIM * HID];
__device__ bf16  g_w2[HID * CDIM];

// ---------------- helpers ----------------------------------------------------
__device__ __forceinline__ uint32_t smem_u32(const void* p) {
    uint32_t a;
    asm("{ .reg .u64 t; cvta.to.shared.u64 t, %1; cvt.u32.u64 %0, t; }" : "=r"(a) : "l"(p));
    return a;
}
#define CP_ASYNC16(dst, src) \
    asm volatile("cp.async.cg.shared.global [%0], [%1], 16;" :: "r"(dst), "l"(src))
#define CP_COMMIT() asm volatile("cp.async.commit_group;" ::: "memory")
#define CP_WAIT(n)  asm volatile("cp.async.wait_group %0;" :: "n"(n) : "memory")

#define LDMATRIX_X4(r0, r1, r2, r3, addr) \
    asm volatile("ldmatrix.sync.aligned.m8n8.x4.shared.b16 {%0,%1,%2,%3}, [%4];" \
                 : "=r"(r0), "=r"(r1), "=r"(r2), "=r"(r3) : "r"(addr))

#define MMA_16816(d, a, b0v, b1v) \
    asm volatile("mma.sync.aligned.m16n8k16.row.col.f32.bf16.bf16.f32 " \
                 "{%0,%1,%2,%3}, {%4,%5,%6,%7}, {%8,%9}, {%0,%1,%2,%3};" \
                 : "+f"((d)[0]), "+f"((d)[1]), "+f"((d)[2]), "+f"((d)[3]) \
                 : "r"((a)[0]), "r"((a)[1]), "r"((a)[2]), "r"((a)[3]), \
                   "r"(b0v), "r"(b1v))

__device__ __forceinline__ int map_win_to_global(int r) {
    int w = r >> 6, n = r & 63;
    int b = w >> 8, rem = w & 255;
    int wh = rem >> 4, ww = rem & 15;
    int i = n >> 3, j = n & 7;
    int h  = (wh * 8 + i + SS) & 127;
    int wc = (ww * 8 + j + SS) & 127;
    return (b << 14) + (h << 7) + wc;
}
__device__ __forceinline__ float gelu_exact(float v) {
    return 0.5f * v * (1.0f + erff(v * 0.70710678118654752440f));
}
__device__ __forceinline__ uint32_t pack_bf2(float a, float b) {
    __nv_bfloat162 h = __floats2bfloat162_rn(a, b);
    return *(uint32_t*)&h;
}

// ---------------- fp32 -> bf16 conversion -------------------------------------
__global__ void __launch_bounds__(256) conv_x_k(const float* __restrict__ src) {
    const size_t i = ((size_t)blockIdx.x * 256 + threadIdx.x) * 8;
    float4 v0 = *(const float4*)(src + i);
    float4 v1 = *(const float4*)(src + i + 4);
    uint4 o;
    o.x = pack_bf2(v0.x, v0.y); o.y = pack_bf2(v0.z, v0.w);
    o.z = pack_bf2(v1.x, v1.y); o.w = pack_bf2(v1.z, v1.w);
    *(uint4*)(g_xbf + i) = o;
}
#define S0 (CDIM*QKVN)
#define S1 (CDIM*CDIM)
#define S2 (CDIM*HID)
#define S3 (HID*CDIM)
__global__ void __launch_bounds__(256) conv_w_all(
    const float* __restrict__ w0, const float* __restrict__ w1,
    const float* __restrict__ w2, const float* __restrict__ w3)
{
    const int off = (blockIdx.x * 256 + threadIdx.x) * 8;
    const float* src; bf16* dst; int lo;
    if      (off < S0)            { src = w0; dst = g_wqkv;  lo = off; }
    else if (off < S0+S1)         { src = w1; dst = g_wproj; lo = off - S0; }
    else if (off < S0+S1+S2)      { src = w2; dst = g_w1;    lo = off - S0 - S1; }
    else if (off < S0+S1+S2+S3)   { src = w3; dst = g_w2;    lo = off - S0 - S1 - S2; }
    else return;
    float4 v0 = *(const float4*)(src + lo);
    float4 v1 = *(const float4*)(src + lo + 4);
    uint4 o;
    o.x = pack_bf2(v0.x, v0.y); o.y = pack_bf2(v0.z, v0.w);
    o.z = pack_bf2(v1.x, v1.y); o.w = pack_bf2(v1.z, v1.w);
    *(uint4*)(dst + lo) = o;
}

// ---------------- WMMA bf16 GEMM: 128x96 block, 64x48 warp tile (R9) ----------
// MODE: 0=QKV(gather A; out bf16 g_qkv)  1=PROJ(scatter+resid -> fp32 g_x1)
//       2=FC1(gelu -> bf16 g_h)          3=FC2(+resid g_x1 -> fp32 Cout)
template<int KDIM, int NDIM, int MODE>
__global__ void __launch_bounds__(128) gemm_bf(
    const float* __restrict__ bias,
    const float* __restrict__ resid,
    float* __restrict__ Cout)
{
    __shared__ __align__(16) unsigned char smem[SMEM_BYTES];
    bf16* sA[2] = { (bf16*)smem, (bf16*)(smem + STAGE_B) };
    bf16* sB[2] = { (bf16*)(smem + A_STAGE_B), (bf16*)(smem + STAGE_B + A_STAGE_B) };
    float* sC = (float*)smem;

    const int tid = threadIdx.x;
    const int bm = blockIdx.y * BM;
    const int bn = blockIdx.x * BN;

    const bf16* Aptr;
    const bf16* Bptr;
    if      constexpr (MODE == 0) { Aptr = g_xbf;     Bptr = g_wqkv; }
    else if constexpr (MODE == 1) { Aptr = g_attnout; Bptr = g_wproj; }
    else if constexpr (MODE == 2) { Aptr = g_x1n;     Bptr = g_w1; }
    else                          { Aptr = g_h;       Bptr = g_w2; }

    int grA;
    if constexpr (MODE == 0) grA = map_win_to_global(bm + tid);
    else                     grA = bm + tid;
    const bf16* srcA = Aptr + (size_t)grA * KDIM;
    const uint32_t dA0 = smem_u32(sA[0]) + (uint32_t)(tid * LDA * 2);
    const uint32_t dA1 = smem_u32(sA[1]) + (uint32_t)(tid * LDA * 2);

    int bRow[3], bCol[3];
    const bf16* srcB[3];
    uint32_t dBoff[3];
    #pragma unroll
    for (int l = 0; l < 3; l++) {
        int idx = tid + l * 128;
        bRow[l] = idx / 12; bCol[l] = (idx % 12) * 8;
        srcB[l] = Bptr + (size_t)bRow[l] * NDIM + bn + bCol[l];
        dBoff[l] = (uint32_t)((bRow[l] * LDB + bCol[l]) * 2);
    }
    const uint32_t dBb[2] = { smem_u32(sB[0]), smem_u32(sB[1]) };

    constexpr int T = KDIM / BK;
    const int wid = tid >> 5;
    const int wm = wid & 1, wn = wid >> 1;

    wmma::fragment<wmma::accumulator, 16, 16, 16, float> cf[4][3];
    #pragma unroll
    for (int i = 0; i < 4; i++)
        #pragma unroll
        for (int j = 0; j < 3; j++) wmma::fill_fragment(cf[i][j], 0.0f);

    #pragma unroll
    for (int c = 0; c < 4; c++) CP_ASYNC16(dA0 + c * 16, srcA + c * 8);
    #pragma unroll
    for (int l = 0; l < 3; l++) CP_ASYNC16(dBb[0] + dBoff[l], srcB[l]);
    CP_COMMIT();

    for (int t = 0; t < T; t++) {
        if (t + 1 < T) {
            const int k0 = (t + 1) * BK;
            const uint32_t dAx = ((t + 1) & 1) ? dA1 : dA0;
            const uint32_t dBx = dBb[(t + 1) & 1];
            #pragma unroll
            for (int c = 0; c < 4; c++) CP_ASYNC16(dAx + c * 16, srcA + k0 + c * 8);
            #pragma unroll
            for (int l = 0; l < 3; l++) CP_ASYNC16(dBx + dBoff[l], srcB[l] + (size_t)k0 * NDIM);
            CP_COMMIT();
            CP_WAIT(1);
        } else {
            CP_WAIT(0);
        }
        __syncthreads();

        const bf16* At = sA[t & 1];
        const bf16* Bt = sB[t & 1];

        #pragma unroll
        for (int kk = 0; kk < BK; kk += 16) {
            wmma::fragment<wmma::matrix_a, 16, 16, 16, bf16, wmma::row_major> af[4];
            wmma::fragment<wmma::matrix_b, 16, 16, 16, bf16, wmma::row_major> bf_[3];
            #pragma unroll
            for (int i = 0; i < 4; i++)
                wmma::load_matrix_sync(af[i], At + (wm * 64 + i * 16) * LDA + kk, LDA);
            #pragma unroll
            for (int j = 0; j < 3; j++)
                wmma::load_matrix_sync(bf_[j], Bt + kk * LDB + wn * 48 + j * 16, LDB);
            #pragma unroll
            for (int i = 0; i < 4; i++)
                #pragma unroll
                for (int j = 0; j < 3; j++)
                    wmma::mma_sync(cf[i][j], af[i], bf_[j], cf[i][j]);
        }
        __syncthreads();
    }

    #pragma unroll
    for (int h = 0; h < 2; h++) {
        if (wm == h) {
            #pragma unroll
            for (int i = 0; i < 4; i++)
                #pragma unroll
                for (int j = 0; j < 3; j++)
                    wmma::store_matrix_sync(sC + (i * 16) * LDC + wn * 48 + j * 16,
                                            cf[i][j], LDC, wmma::mem_row_major);
        }
        __syncthreads();

        const int row  = tid >> 1;
        const int half = tid & 1;
        const int c0   = half * 48;
        const int m    = bm + h * 64 + row;
        float v[48];
        #pragma unroll
        for (int c4 = 0; c4 < 12; c4++) {
            float4 w4 = *(const float4*)(sC + row * LDC + c0 + c4 * 4);
            const int gc = bn + c0 + c4 * 4;
            v[c4*4+0] = w4.x + __ldg(bias + gc + 0);
            v[c4*4+1] = w4.y + __ldg(bias + gc + 1);
            v[c4*4+2] = w4.z + __ldg(bias + gc + 2);
            v[c4*4+3] = w4.w + __ldg(bias + gc + 3);
        }

        if constexpr (MODE == 0) {
            bf16* dst = g_qkv + (size_t)m * QKVN + bn + c0;
            #pragma unroll
            for (int g = 0; g < 6; g++) {
                uint4 o;
                o.x = pack_bf2(v[g*8+0], v[g*8+1]); o.y = pack_bf2(v[g*8+2], v[g*8+3]);
                o.z = pack_bf2(v[g*8+4], v[g*8+5]); o.w = pack_bf2(v[g*8+6], v[g*8+7]);
                *(uint4*)(dst + g * 8) = o;
            }
        } else if constexpr (MODE == 1) {
            const int grow = map_win_to_global(m);
            const size_t o = (size_t)grow * CDIM + bn + c0;
            #pragma unroll
            for (int c4 = 0; c4 < 12; c4++) {
                float4 r = *(const float4*)(resid + o + c4 * 4);
                *(float4*)(g_x1 + o + c4 * 4) =
                    make_float4(v[c4*4+0] + r.x, v[c4*4+1] + r.y, v[c4*4+2] + r.z, v[c4*4+3] + r.w);
            }
        } else if constexpr (MODE == 2) {
            bf16* dst = g_h + (size_t)m * HID + bn + c0;
            #pragma unroll
            for (int g = 0; g < 6; g++) {
                uint4 o;
                o.x = pack_bf2(gelu_exact(v[g*8+0]), gelu_exact(v[g*8+1]));
                o.y = pack_bf2(gelu_exact(v[g*8+2]), gelu_exact(v[g*8+3]));
                o.z = pack_bf2(gelu_exact(v[g*8+4]), gelu_exact(v[g*8+5]));
                o.w = pack_bf2(gelu_exact(v[g*8+6]), gelu_exact(v[g*8+7]));
                *(uint4*)(dst + g * 8) = o;
            }
        } else {
            const size_t o = (size_t)m * CDIM + bn + c0;
            #pragma unroll
            for (int c4 = 0; c4 < 12; c4++) {
                float4 r = *(const float4*)(g_x1 + o + c4 * 4);
                *(float4*)(Cout + o + c4 * 4) =
                    make_float4(v[c4*4+0] + r.x, v[c4*4+1] + r.y, v[c4*4+2] + r.z, v[c4*4+3] + r.w);
            }
        }
        __syncthreads();
    }
}

// ---------------- LayerNorm: one warp per token, bf16 out ---------------------
__global__ void __launch_bounds__(256) ln_norm_k(const float* __restrict__ gamma,
                                                 const float* __restrict__ beta)
{
    const int r = blockIdx.x * 8 + (threadIdx.x >> 5);
    const int lane = threadIdx.x & 31;
    const float* p = g_x1 + (size_t)r * CDIM;
    float v[6];
    float s = 0.f, ss = 0.f;
    #pragma unroll
    for (int k = 0; k < 6; k++) {
        v[k] = p[lane + k * 32];
        s += v[k]; ss += v[k] * v[k];
    }
    #pragma unroll
    for (int o = 16; o; o >>= 1) {
        s  += __shfl_xor_sync(0xffffffffu, s,  o);
        ss += __shfl_xor_sync(0xffffffffu, ss, o);
    }
    const float mu = s * (1.f / 192.f);
    const float var = ss * (1.f / 192.f) - mu * mu;
    const float rs = rsqrtf(var + 1e-5f);
    bf16* q = g_x1n + (size_t)r * CDIM;
    #pragma unroll
    for (int k = 0; k < 6; k++) {
        const int c = lane + k * 32;
        q[c] = __float2bfloat16_rn((v[k] - mu) * rs * __ldg(gamma + c) + __ldg(beta + c));
    }
}

// ---------------- attention: register-resident S (raw mma.m16n8k16) ----------
// One block = (window, head). 4 warps; warp owns 16 query rows.
// S accumulated in registers; softmax in registers (acc layout == A-operand
// layout for the PV mma); V transposed in smem so both GEMMs use plain ldmatrix.
#define ALQ 40     // sQ/sK row stride (bf16)
#define LVT 72     // sVt row stride (bf16): 32 dims x 64 keys

__global__ void __launch_bounds__(128) attn_tc(const float* __restrict__ rpb)
{
    const int w = blockIdx.x, head = blockIdx.y;
    const int tid = threadIdx.x;
    const int wid = tid >> 5, lane = tid & 31;

    __shared__ __align__(16) bf16 sQ[64 * ALQ];
    __shared__ __align__(16) bf16 sK[64 * ALQ];
    __shared__ __align__(16) bf16 sVt[32 * LVT];
    __shared__ float sRp[225];
    __shared__ int   sReg[64];

    // ---- load Q,K (row-major), V transposed
    const bf16* base = g_qkv + (size_t)w * 64 * QKVN + head * 32;
    #pragma unroll
    for (int l = 0; l < 2; l++) {
        int i = tid + l * 128;
        int row = i >> 2, cg = (i & 3) * 8;
        const bf16* src = base + (size_t)row * QKVN;
        *(uint4*)(sQ + row * ALQ + cg) = *(const uint4*)(src + cg);
        *(uint4*)(sK + row * ALQ + cg) = *(const uint4*)(src + CDIM + cg);
        uint4 vv = *(const uint4*)(src + 2 * CDIM + cg);
        const bf16* pv = (const bf16*)&vv;
        #pragma unroll
        for (int u = 0; u < 8; u++) sVt[(cg + u) * LVT + row] = pv[u];
    }
    for (int i = tid; i < 225; i += 128) sRp[i] = rpb[i * NHEAD + head];
    if (tid < 64) {
        int rem = w & 255; int wh = rem >> 4, ww = rem & 15;
        int hs  = wh * 8 + (tid >> 3);
        int wsc = ww * 8 + (tid & 7);
        int rh = hs  < 120 ? 0 : (hs  < 124 ? 1 : 2);
        int rw = wsc < 120 ? 0 : (wsc < 124 ? 1 : 2);
        sReg[tid] = rh * 3 + rw;
    }
    __syncthreads();

    const int r0 = wid * 16;
    const int qr = lane >> 2;      // 0..7
    const int qc = lane & 3;       // 0..3
    const uint32_t sQa = smem_u32(sQ), sKa = smem_u32(sK), sVa = smem_u32(sVt);

    // ---- A fragments of Q: frag kk covers dims 16kk..16kk+16
    uint32_t aq[2][4];
    #pragma unroll
    for (int kk = 0; kk < 2; kk++) {
        uint32_t addr = sQa + (uint32_t)((r0 + (lane & 15)) * ALQ * 2 + kk * 32 + (lane >> 4) * 16);
        LDMATRIX_X4(aq[kk][0], aq[kk][1], aq[kk][2], aq[kk][3], addr);
    }

    // ---- S = Q @ K^T : 8 n8-tiles of keys
    float acc[8][4];
    #pragma unroll
    for (int nb = 0; nb < 8; nb++) {
        acc[nb][0] = acc[nb][1] = acc[nb][2] = acc[nb][3] = 0.f;
        uint32_t kb0, kb1, kb2, kb3;
        uint32_t addr = sKa + (uint32_t)((8 * nb + (lane & 7)) * ALQ * 2 + (lane >> 3) * 16);
        LDMATRIX_X4(kb0, kb1, kb2, kb3, addr);
        MMA_16816(acc[nb], aq[0], kb0, kb1);
        MMA_16816(acc[nb], aq[1], kb2, kb3);
    }

    // ---- softmax in registers (no max-subtract; masked -> exp ~ 0)
    const int grow0 = r0 + qr, grow1 = grow0 + 8;
    const int i10 = grow0 >> 3, j10 = grow0 & 7, reg0 = sReg[grow0];
    const int i11 = grow1 >> 3, j11 = grow1 & 7, reg1 = sReg[grow1];
    const float scale = 0.17677669529663689f;
    float sum0 = 0.f, sum1 = 0.f;
    #pragma unroll
    for (int nb = 0; nb < 8; nb++) {
        #pragma unroll
        for (int e = 0; e < 2; e++) {
            const int c = 8 * nb + 2 * qc + e;
            const int j2 = c & 7;
            const int rc = sReg[c];
            const float m0 = (rc == reg0) ? 0.f : -100.f;
            const float m1 = (rc == reg1) ? 0.f : -100.f;
            const float b0 = sRp[(i10 - nb + 7) * 15 + (j10 - j2 + 7)];
            const float b1 = sRp[(i11 - nb + 7) * 15 + (j11 - j2 + 7)];
            float e0 = __expf(acc[nb][e]     * scale + b0 + m0);
            float e1 = __expf(acc[nb][2 + e] * scale + b1 + m1);
            acc[nb][e] = e0;     sum0 += e0;
            acc[nb][2 + e] = e1; sum1 += e1;
        }
    }
    sum0 += __shfl_xor_sync(0xffffffffu, sum0, 1);
    sum0 += __shfl_xor_sync(0xffffffffu, sum0, 2);
    sum1 += __shfl_xor_sync(0xffffffffu, sum1, 1);
    sum1 += __shfl_xor_sync(0xffffffffu, sum1, 2);
    const float inv0 = 1.f / sum0, inv1 = 1.f / sum1;

    // ---- P packed directly into A-operand fragments (acc layout == A layout)
    uint32_t pa[4][4];
    #pragma unroll
    for (int kk = 0; kk < 4; kk++) {
        const int na = 2 * kk, nbb = 2 * kk + 1;
        pa[kk][0] = pack_bf2(acc[na][0] * inv0, acc[na][1] * inv0);
        pa[kk][1] = pack_bf2(acc[na][2] * inv1, acc[na][3] * inv1);
        pa[kk][2] = pack_bf2(acc[nbb][0] * inv0, acc[nbb][1] * inv0);
        pa[kk][3] = pack_bf2(acc[nbb][2] * inv1, acc[nbb][3] * inv1);
    }

    // ---- O = P @ V : 4 n8-tiles of dims, k = 64 keys (4 chunks)
    float oacc[4][4];
    #pragma unroll
    for (int nd = 0; nd < 4; nd++) {
        oacc[nd][0] = oacc[nd][1] = oacc[nd][2] = oacc[nd][3] = 0.f;
        uint32_t vb0, vb1, vb2, vb3;
        uint32_t addr = sVa + (uint32_t)((8 * nd + (lane & 7)) * LVT * 2 + (lane >> 3) * 16);
        LDMATRIX_X4(vb0, vb1, vb2, vb3, addr);           // keys 0..31
        MMA_16816(oacc[nd], pa[0], vb0, vb1);
        MMA_16816(oacc[nd], pa[1], vb2, vb3);
        LDMATRIX_X4(vb0, vb1, vb2, vb3, addr + 64);      // keys 32..63
        MMA_16816(oacc[nd], pa[2], vb0, vb1);
        MMA_16816(oacc[nd], pa[3], vb2, vb3);
    }

    // ---- write bf16 output (row-pair per thread)
    bf16* op0 = g_attnout + ((size_t)(w * 64 + grow0)) * CDIM + head * 32 + 2 * qc;
    bf16* op1 = g_attnout + ((size_t)(w * 64 + grow1)) * CDIM + head * 32 + 2 * qc;
    #pragma unroll
    for (int nd = 0; nd < 4; nd++) {
        *(uint32_t*)(op0 + 8 * nd) = pack_bf2(oacc[nd][0], oacc[nd][1]);
        *(uint32_t*)(op1 + 8 * nd) = pack_bf2(oacc[nd][2], oacc[nd][3]);
    }
}

// ---------------- launch -----------------------------------------------------
extern "C" void kernel_launch(void* const* d_in, const int* in_sizes, int n_in,
                              void* d_out, int out_size)
{
    const float* x       = (const float*)d_in[0];
    const float* qkv_w   = (const float*)d_in[1];
    const float* qkv_b   = (const float*)d_in[2];
    const float* proj_w  = (const float*)d_in[3];
    const float* proj_b  = (const float*)d_in[4];
    const float* rpb     = (const float*)d_in[5];
    const float* norm2_g = (const float*)d_in[6];
    const float* norm2_b = (const float*)d_in[7];
    const float* mlp_w1  = (const float*)d_in[8];
    const float* mlp_b1  = (const float*)d_in[9];
    const float* mlp_w2  = (const float*)d_in[10];
    const float* mlp_b2  = (const float*)d_in[11];
    float* out = (float*)d_out;

    // precision conversions
    conv_x_k<<<TOK * CDIM / (256 * 8), 256>>>(x);
    conv_w_all<<<(S0 + S1 + S2 + S3) / (256 * 8), 256>>>(qkv_w, proj_w, mlp_w1, mlp_w2);

    // 1) QKV = gather(x) @ qkv_w + b  -> bf16 g_qkv (window order)
    gemm_bf<192, 576, 0><<<dim3(6, 1024), 128>>>(qkv_b, nullptr, nullptr);
    // 2) windowed attention (register-resident softmax) -> bf16 g_attnout
    attn_tc<<<dim3(NWIN, NHEAD), 128>>>(rpb);
    // 3) proj + scatter + residual -> fp32 g_x1
    gemm_bf<192, 192, 1><<<dim3(2, 1024), 128>>>(proj_b, x, nullptr);
    // 4) LayerNorm(g_x1) -> bf16 g_x1n
    ln_norm_k<<<TOK / 8, 256>>>(norm2_g, norm2_b);
    // 5) fc1 + GELU -> bf16 g_h
    gemm_bf<192, 768, 2><<<dim3(8, 1024), 128>>>(mlp_b1, nullptr, nullptr);
    // 6) fc2 + residual -> fp32 out
    gemm_bf<768, 192, 3><<<dim3(2, 1024), 128>>>(mlp_b2, nullptr, out);
}

// round 14
// speedup vs baseline: 1.1379x; 1.0047x over previous
#include <cuda_runtime.h>
#include <cuda_bf16.h>
#include <mma.h>
#include <cstdint>
#include <math.h>

using namespace nvcuda;
typedef __nv_bfloat16 bf16;

// Problem constants (fixed shapes)
#define TOK   131072      // B*H*W = 8*128*128
#define CDIM  192
#define HID   768
#define QKVN  576
#define NHEAD 6
#define SS    4
#define NWIN  2048        // B * 16 * 16

// GEMM tiling: block 128x96, 4 warps (2m x 2n), warp tile 64x48  (R9/R12 proven)
#define BM 128
#define BN 96
#define BK 32
#define LDA 40            // bf16 ld, 80B rows
#define LDB 104           // bf16 ld for B (96+8)
#define LDC 100           // fp32 ld for C half-tile
#define A_STAGE_B (BM * LDA * 2)      // 10240 B
#define B_STAGE_B (BK * LDB * 2)      // 6656 B
#define STAGE_B   (A_STAGE_B + B_STAGE_B)
#define SMEM_BYTES (2 * STAGE_B)      // 33792; C half-tile 64*100*4=25600 fits

// ---------------- scratch (device globals; no allocations allowed) ----------
__device__ bf16  g_xbf[TOK * CDIM];
__device__ bf16  g_qkv[TOK * QKVN];        // window-ordered, bf16
__device__ bf16  g_attnout[TOK * CDIM];    // window-ordered, bf16
__device__ float g_x1[TOK * CDIM];         // fp32 residual spine
__device__ bf16  g_x1n[TOK * CDIM];
__device__ bf16  g_h[TOK * HID];
__device__ bf16  g_wqkv[CDIM * QKVN];
__device__ bf16  g_wproj[CDIM * CDIM];
__device__ bf16  g_w1[CDIM * HID];
__device__ bf16  g_w2[HID * CDIM];

// ---------------- helpers ----------------------------------------------------
__device__ __forceinline__ uint32_t smem_u32(const void* p) {
    uint32_t a;
    asm("{ .reg .u64 t; cvta.to.shared.u64 t, %1; cvt.u32.u64 %0, t; }" : "=r"(a) : "l"(p));
    return a;
}
#define CP_ASYNC16(dst, src) \
    asm volatile("cp.async.cg.shared.global [%0], [%1], 16;" :: "r"(dst), "l"(src))
#define CP_COMMIT() asm volatile("cp.async.commit_group;" ::: "memory")
#define CP_WAIT(n)  asm volatile("cp.async.wait_group %0;" :: "n"(n) : "memory")

#define LDMATRIX_X4(r0, r1, r2, r3, addr) \
    asm volatile("ldmatrix.sync.aligned.m8n8.x4.shared.b16 {%0,%1,%2,%3}, [%4];" \
                 : "=r"(r0), "=r"(r1), "=r"(r2), "=r"(r3) : "r"(addr))
#define LDMATRIX_X4_T(r0, r1, r2, r3, addr) \
    asm volatile("ldmatrix.sync.aligned.m8n8.x4.trans.shared.b16 {%0,%1,%2,%3}, [%4];" \
                 : "=r"(r0), "=r"(r1), "=r"(r2), "=r"(r3) : "r"(addr))

#define MMA_16816(d, a, b0v, b1v) \
    asm volatile("mma.sync.aligned.m16n8k16.row.col.f32.bf16.bf16.f32 " \
                 "{%0,%1,%2,%3}, {%4,%5,%6,%7}, {%8,%9}, {%0,%1,%2,%3};" \
                 : "+f"((d)[0]), "+f"((d)[1]), "+f"((d)[2]), "+f"((d)[3]) \
                 : "r"((a)[0]), "r"((a)[1]), "r"((a)[2]), "r"((a)[3]), \
                   "r"(b0v), "r"(b1v))

__device__ __forceinline__ int map_win_to_global(int r) {
    int w = r >> 6, n = r & 63;
    int b = w >> 8, rem = w & 255;
    int wh = rem >> 4, ww = rem & 15;
    int i = n >> 3, j = n & 7;
    int h  = (wh * 8 + i + SS) & 127;
    int wc = (ww * 8 + j + SS) & 127;
    return (b << 14) + (h << 7) + wc;
}
__device__ __forceinline__ float gelu_exact(float v) {
    return 0.5f * v * (1.0f + erff(v * 0.70710678118654752440f));
}
__device__ __forceinline__ uint32_t pack_bf2(float a, float b) {
    __nv_bfloat162 h = __floats2bfloat162_rn(a, b);
    return *(uint32_t*)&h;
}

// ---------------- fp32 -> bf16 conversion -------------------------------------
__global__ void __launch_bounds__(256) conv_x_k(const float* __restrict__ src) {
    const size_t i = ((size_t)blockIdx.x * 256 + threadIdx.x) * 8;
    float4 v0 = *(const float4*)(src + i);
    float4 v1 = *(const float4*)(src + i + 4);
    uint4 o;
    o.x = pack_bf2(v0.x, v0.y); o.y = pack_bf2(v0.z, v0.w);
    o.z = pack_bf2(v1.x, v1.y); o.w = pack_bf2(v1.z, v1.w);
    *(uint4*)(g_xbf + i) = o;
}
#define S0 (CDIM*QKVN)
#define S1 (CDIM*CDIM)
#define S2 (CDIM*HID)
#define S3 (HID*CDIM)
__global__ void __launch_bounds__(256) conv_w_all(
    const float* __restrict__ w0, const float* __restrict__ w1,
    const float* __restrict__ w2, const float* __restrict__ w3)
{
    const int off = (blockIdx.x * 256 + threadIdx.x) * 8;
    const float* src; bf16* dst; int lo;
    if      (off < S0)            { src = w0; dst = g_wqkv;  lo = off; }
    else if (off < S0+S1)         { src = w1; dst = g_wproj; lo = off - S0; }
    else if (off < S0+S1+S2)      { src = w2; dst = g_w1;    lo = off - S0 - S1; }
    else if (off < S0+S1+S2+S3)   { src = w3; dst = g_w2;    lo = off - S0 - S1 - S2; }
    else return;
    float4 v0 = *(const float4*)(src + lo);
    float4 v1 = *(const float4*)(src + lo + 4);
    uint4 o;
    o.x = pack_bf2(v0.x, v0.y); o.y = pack_bf2(v0.z, v0.w);
    o.z = pack_bf2(v1.x, v1.y); o.w = pack_bf2(v1.z, v1.w);
    *(uint4*)(dst + lo) = o;
}

// ---------------- WMMA bf16 GEMM: 128x96 block, two-sync mainloop (R12) -------
// MODE: 0=QKV(gather A; out bf16 g_qkv)  1=PROJ(scatter+resid -> fp32 g_x1)
//       2=FC1(gelu -> bf16 g_h)          3=FC2(+resid g_x1 -> fp32 Cout)
template<int KDIM, int NDIM, int MODE>
__global__ void __launch_bounds__(128) gemm_bf(
    const float* __restrict__ bias,
    const float* __restrict__ resid,
    float* __restrict__ Cout)
{
    __shared__ __align__(16) unsigned char smem[SMEM_BYTES];
    bf16* sA[2] = { (bf16*)smem, (bf16*)(smem + STAGE_B) };
    bf16* sB[2] = { (bf16*)(smem + A_STAGE_B), (bf16*)(smem + STAGE_B + A_STAGE_B) };
    float* sC = (float*)smem;

    const int tid = threadIdx.x;
    const int bm = blockIdx.y * BM;
    const int bn = blockIdx.x * BN;

    const bf16* Aptr;
    const bf16* Bptr;
    if      constexpr (MODE == 0) { Aptr = g_xbf;     Bptr = g_wqkv; }
    else if constexpr (MODE == 1) { Aptr = g_attnout; Bptr = g_wproj; }
    else if constexpr (MODE == 2) { Aptr = g_x1n;     Bptr = g_w1; }
    else                          { Aptr = g_h;       Bptr = g_w2; }

    int grA;
    if constexpr (MODE == 0) grA = map_win_to_global(bm + tid);
    else                     grA = bm + tid;
    const bf16* srcA = Aptr + (size_t)grA * KDIM;
    const uint32_t dA0 = smem_u32(sA[0]) + (uint32_t)(tid * LDA * 2);
    const uint32_t dA1 = smem_u32(sA[1]) + (uint32_t)(tid * LDA * 2);

    int bRow[3], bCol[3];
    const bf16* srcB[3];
    uint32_t dBoff[3];
    #pragma unroll
    for (int l = 0; l < 3; l++) {
        int idx = tid + l * 128;
        bRow[l] = idx / 12; bCol[l] = (idx % 12) * 8;
        srcB[l] = Bptr + (size_t)bRow[l] * NDIM + bn + bCol[l];
        dBoff[l] = (uint32_t)((bRow[l] * LDB + bCol[l]) * 2);
    }
    const uint32_t dBb[2] = { smem_u32(sB[0]), smem_u32(sB[1]) };

    constexpr int T = KDIM / BK;
    const int wid = tid >> 5;
    const int wm = wid & 1, wn = wid >> 1;

    wmma::fragment<wmma::accumulator, 16, 16, 16, float> cf[4][3];
    #pragma unroll
    for (int i = 0; i < 4; i++)
        #pragma unroll
        for (int j = 0; j < 3; j++) wmma::fill_fragment(cf[i][j], 0.0f);

    #pragma unroll
    for (int c = 0; c < 4; c++) CP_ASYNC16(dA0 + c * 16, srcA + c * 8);
    #pragma unroll
    for (int l = 0; l < 3; l++) CP_ASYNC16(dBb[0] + dBoff[l], srcB[l]);
    CP_COMMIT();

    for (int t = 0; t < T; t++) {
        if (t + 1 < T) {
            const int k0 = (t + 1) * BK;
            const uint32_t dAx = ((t + 1) & 1) ? dA1 : dA0;
            const uint32_t dBx = dBb[(t + 1) & 1];
            #pragma unroll
            for (int c = 0; c < 4; c++) CP_ASYNC16(dAx + c * 16, srcA + k0 + c * 8);
            #pragma unroll
            for (int l = 0; l < 3; l++) CP_ASYNC16(dBx + dBoff[l], srcB[l] + (size_t)k0 * NDIM);
            CP_COMMIT();
            CP_WAIT(1);
        } else {
            CP_WAIT(0);
        }
        __syncthreads();

        const bf16* At = sA[t & 1];
        const bf16* Bt = sB[t & 1];

        #pragma unroll
        for (int kk = 0; kk < BK; kk += 16) {
            wmma::fragment<wmma::matrix_a, 16, 16, 16, bf16, wmma::row_major> af[4];
            wmma::fragment<wmma::matrix_b, 16, 16, 16, bf16, wmma::row_major> bf_[3];
            #pragma unroll
            for (int i = 0; i < 4; i++)
                wmma::load_matrix_sync(af[i], At + (wm * 64 + i * 16) * LDA + kk, LDA);
            #pragma unroll
            for (int j = 0; j < 3; j++)
                wmma::load_matrix_sync(bf_[j], Bt + kk * LDB + wn * 48 + j * 16, LDB);
            #pragma unroll
            for (int i = 0; i < 4; i++)
                #pragma unroll
                for (int j = 0; j < 3; j++)
                    wmma::mma_sync(cf[i][j], af[i], bf_[j], cf[i][j]);
        }
        __syncthreads();
    }

    #pragma unroll
    for (int h = 0; h < 2; h++) {
        if (wm == h) {
            #pragma unroll
            for (int i = 0; i < 4; i++)
                #pragma unroll
                for (int j = 0; j < 3; j++)
                    wmma::store_matrix_sync(sC + (i * 16) * LDC + wn * 48 + j * 16,
                                            cf[i][j], LDC, wmma::mem_row_major);
        }
        __syncthreads();

        const int row  = tid >> 1;
        const int half = tid & 1;
        const int c0   = half * 48;
        const int m    = bm + h * 64 + row;
        float v[48];
        #pragma unroll
        for (int c4 = 0; c4 < 12; c4++) {
            float4 w4 = *(const float4*)(sC + row * LDC + c0 + c4 * 4);
            const int gc = bn + c0 + c4 * 4;
            v[c4*4+0] = w4.x + __ldg(bias + gc + 0);
            v[c4*4+1] = w4.y + __ldg(bias + gc + 1);
            v[c4*4+2] = w4.z + __ldg(bias + gc + 2);
            v[c4*4+3] = w4.w + __ldg(bias + gc + 3);
        }

        if constexpr (MODE == 0) {
            bf16* dst = g_qkv + (size_t)m * QKVN + bn + c0;
            #pragma unroll
            for (int g = 0; g < 6; g++) {
                uint4 o;
                o.x = pack_bf2(v[g*8+0], v[g*8+1]); o.y = pack_bf2(v[g*8+2], v[g*8+3]);
                o.z = pack_bf2(v[g*8+4], v[g*8+5]); o.w = pack_bf2(v[g*8+6], v[g*8+7]);
                *(uint4*)(dst + g * 8) = o;
            }
        } else if constexpr (MODE == 1) {
            const int grow = map_win_to_global(m);
            const size_t o = (size_t)grow * CDIM + bn + c0;
            #pragma unroll
            for (int c4 = 0; c4 < 12; c4++) {
                float4 r = *(const float4*)(resid + o + c4 * 4);
                *(float4*)(g_x1 + o + c4 * 4) =
                    make_float4(v[c4*4+0] + r.x, v[c4*4+1] + r.y, v[c4*4+2] + r.z, v[c4*4+3] + r.w);
            }
        } else if constexpr (MODE == 2) {
            bf16* dst = g_h + (size_t)m * HID + bn + c0;
            #pragma unroll
            for (int g = 0; g < 6; g++) {
                uint4 o;
                o.x = pack_bf2(gelu_exact(v[g*8+0]), gelu_exact(v[g*8+1]));
                o.y = pack_bf2(gelu_exact(v[g*8+2]), gelu_exact(v[g*8+3]));
                o.z = pack_bf2(gelu_exact(v[g*8+4]), gelu_exact(v[g*8+5]));
                o.w = pack_bf2(gelu_exact(v[g*8+6]), gelu_exact(v[g*8+7]));
                *(uint4*)(dst + g * 8) = o;
            }
        } else {
            const size_t o = (size_t)m * CDIM + bn + c0;
            #pragma unroll
            for (int c4 = 0; c4 < 12; c4++) {
                float4 r = *(const float4*)(g_x1 + o + c4 * 4);
                *(float4*)(Cout + o + c4 * 4) =
                    make_float4(v[c4*4+0] + r.x, v[c4*4+1] + r.y, v[c4*4+2] + r.z, v[c4*4+3] + r.w);
            }
        }
        __syncthreads();
    }
}

// ---------------- LayerNorm: one warp per token, bf16 out ---------------------
__global__ void __launch_bounds__(256) ln_norm_k(const float* __restrict__ gamma,
                                                 const float* __restrict__ beta)
{
    const int r = blockIdx.x * 8 + (threadIdx.x >> 5);
    const int lane = threadIdx.x & 31;
    const float* p = g_x1 + (size_t)r * CDIM;
    float v[6];
    float s = 0.f, ss = 0.f;
    #pragma unroll
    for (int k = 0; k < 6; k++) {
        v[k] = p[lane + k * 32];
        s += v[k]; ss += v[k] * v[k];
    }
    #pragma unroll
    for (int o = 16; o; o >>= 1) {
        s  += __shfl_xor_sync(0xffffffffu, s,  o);
        ss += __shfl_xor_sync(0xffffffffu, ss, o);
    }
    const float mu = s * (1.f / 192.f);
    const float var = ss * (1.f / 192.f) - mu * mu;
    const float rs = rsqrtf(var + 1e-5f);
    bf16* q = g_x1n + (size_t)r * CDIM;
    #pragma unroll
    for (int k = 0; k < 6; k++) {
        const int c = lane + k * 32;
        q[c] = __float2bfloat16_rn((v[k] - mu) * rs * __ldg(gamma + c) + __ldg(beta + c));
    }
}

// ---------------- attention: register-resident S, trans-ldmatrix V ------------
#define ALQ 40     // sQ/sK/sV row stride (bf16); 80B rows (16B-aligned)

__global__ void __launch_bounds__(128) attn_tc(const float* __restrict__ rpb)
{
    const int w = blockIdx.x, head = blockIdx.y;
    const int tid = threadIdx.x;
    const int wid = tid >> 5, lane = tid & 31;

    __shared__ __align__(16) bf16 sQ[64 * ALQ];
    __shared__ __align__(16) bf16 sK[64 * ALQ];
    __shared__ __align__(16) bf16 sV[64 * ALQ];
    __shared__ float sRp[225];
    __shared__ int   sReg[64];

    // ---- load Q,K,V row-major (uint4 copies; no transpose stores)
    const bf16* base = g_qkv + (size_t)w * 64 * QKVN + head * 32;
    #pragma unroll
    for (int l = 0; l < 2; l++) {
        int i = tid + l * 128;
        int row = i >> 2, cg = (i & 3) * 8;
        const bf16* src = base + (size_t)row * QKVN;
        *(uint4*)(sQ + row * ALQ + cg) = *(const uint4*)(src + cg);
        *(uint4*)(sK + row * ALQ + cg) = *(const uint4*)(src + CDIM + cg);
        *(uint4*)(sV + row * ALQ + cg) = *(const uint4*)(src + 2 * CDIM + cg);
    }
    for (int i = tid; i < 225; i += 128) sRp[i] = rpb[i * NHEAD + head];
    if (tid < 64) {
        int rem = w & 255; int wh = rem >> 4, ww = rem & 15;
        int hs  = wh * 8 + (tid >> 3);
        int wsc = ww * 8 + (tid & 7);
        int rh = hs  < 120 ? 0 : (hs  < 124 ? 1 : 2);
        int rw = wsc < 120 ? 0 : (wsc < 124 ? 1 : 2);
        sReg[tid] = rh * 3 + rw;
    }
    __syncthreads();

    const int r0 = wid * 16;
    const int qr = lane >> 2;      // 0..7
    const int qc = lane & 3;       // 0..3
    const uint32_t sQa = smem_u32(sQ), sKa = smem_u32(sK), sVa = smem_u32(sV);

    // ---- A fragments of Q
    uint32_t aq[2][4];
    #pragma unroll
    for (int kk = 0; kk < 2; kk++) {
        uint32_t addr = sQa + (uint32_t)((r0 + (lane & 15)) * ALQ * 2 + kk * 32 + (lane >> 4) * 16);
        LDMATRIX_X4(aq[kk][0], aq[kk][1], aq[kk][2], aq[kk][3], addr);
    }

    // ---- S = Q @ K^T : 8 n8-tiles of keys
    float acc[8][4];
    #pragma unroll
    for (int nb = 0; nb < 8; nb++) {
        acc[nb][0] = acc[nb][1] = acc[nb][2] = acc[nb][3] = 0.f;
        uint32_t kb0, kb1, kb2, kb3;
        uint32_t addr = sKa + (uint32_t)((8 * nb + (lane & 7)) * ALQ * 2 + (lane >> 3) * 16);
        LDMATRIX_X4(kb0, kb1, kb2, kb3, addr);
        MMA_16816(acc[nb], aq[0], kb0, kb1);
        MMA_16816(acc[nb], aq[1], kb2, kb3);
    }

    // ---- softmax in registers (no max-subtract; masked -> exp ~ 0)
    const int grow0 = r0 + qr, grow1 = grow0 + 8;
    const int i10 = grow0 >> 3, j10 = grow0 & 7, reg0 = sReg[grow0];
    const int i11 = grow1 >> 3, j11 = grow1 & 7, reg1 = sReg[grow1];
    const float scale = 0.17677669529663689f;
    float sum0 = 0.f, sum1 = 0.f;
    #pragma unroll
    for (int nb = 0; nb < 8; nb++) {
        #pragma unroll
        for (int e = 0; e < 2; e++) {
            const int c = 8 * nb + 2 * qc + e;
            const int j2 = c & 7;
            const int rc = sReg[c];
            const float m0 = (rc == reg0) ? 0.f : -100.f;
            const float m1 = (rc == reg1) ? 0.f : -100.f;
            const float b0 = sRp[(i10 - nb + 7) * 15 + (j10 - j2 + 7)];
            const float b1 = sRp[(i11 - nb + 7) * 15 + (j11 - j2 + 7)];
            float e0 = __expf(acc[nb][e]     * scale + b0 + m0);
            float e1 = __expf(acc[nb][2 + e] * scale + b1 + m1);
            acc[nb][e] = e0;     sum0 += e0;
            acc[nb][2 + e] = e1; sum1 += e1;
        }
    }
    sum0 += __shfl_xor_sync(0xffffffffu, sum0, 1);
    sum0 += __shfl_xor_sync(0xffffffffu, sum0, 2);
    sum1 += __shfl_xor_sync(0xffffffffu, sum1, 1);
    sum1 += __shfl_xor_sync(0xffffffffu, sum1, 2);
    const float inv0 = 1.f / sum0, inv1 = 1.f / sum1;

    // ---- P packed into A-operand fragments (acc layout == A layout)
    uint32_t pa[4][4];
    #pragma unroll
    for (int kk = 0; kk < 4; kk++) {
        const int na = 2 * kk, nbb = 2 * kk + 1;
        pa[kk][0] = pack_bf2(acc[na][0] * inv0, acc[na][1] * inv0);
        pa[kk][1] = pack_bf2(acc[na][2] * inv1, acc[na][3] * inv1);
        pa[kk][2] = pack_bf2(acc[nbb][0] * inv0, acc[nbb][1] * inv0);
        pa[kk][3] = pack_bf2(acc[nbb][2] * inv1, acc[nbb][3] * inv1);
    }

    // ---- O = P @ V : trans-ldmatrix straight from row-major V
    // x4.trans, lanes 0..31 -> key rows (k0..k31 / k32..k63), column offset 8*nd:
    // yields B-fragments (keys x dims) in the same register order as the
    // explicit-transpose path that passed in R12.
    float oacc[4][4];
    #pragma unroll
    for (int nd = 0; nd < 4; nd++) {
        oacc[nd][0] = oacc[nd][1] = oacc[nd][2] = oacc[nd][3] = 0.f;
        uint32_t vb0, vb1, vb2, vb3;
        uint32_t addr = sVa + (uint32_t)(lane * ALQ * 2 + nd * 16);
        LDMATRIX_X4_T(vb0, vb1, vb2, vb3, addr);                 // keys 0..31
        MMA_16816(oacc[nd], pa[0], vb0, vb1);
        MMA_16816(oacc[nd], pa[1], vb2, vb3);
        addr = sVa + (uint32_t)((32 + lane) * ALQ * 2 + nd * 16);
        LDMATRIX_X4_T(vb0, vb1, vb2, vb3, addr);                 // keys 32..63
        MMA_16816(oacc[nd], pa[2], vb0, vb1);
        MMA_16816(oacc[nd], pa[3], vb2, vb3);
    }

    // ---- write bf16 output (row-pair per thread)
    bf16* op0 = g_attnout + ((size_t)(w * 64 + grow0)) * CDIM + head * 32 + 2 * qc;
    bf16* op1 = g_attnout + ((size_t)(w * 64 + grow1)) * CDIM + head * 32 + 2 * qc;
    #pragma unroll
    for (int nd = 0; nd < 4; nd++) {
        *(uint32_t*)(op0 + 8 * nd) = pack_bf2(oacc[nd][0], oacc[nd][1]);
        *(uint32_t*)(op1 + 8 * nd) = pack_bf2(oacc[nd][2], oacc[nd][3]);
    }
}

// ---------------- launch -----------------------------------------------------
extern "C" void kernel_launch(void* const* d_in, const int* in_sizes, int n_in,
                              void* d_out, int out_size)
{
    const float* x       = (const float*)d_in[0];
    const float* qkv_w   = (const float*)d_in[1];
    const float* qkv_b   = (const float*)d_in[2];
    const float* proj_w  = (const float*)d_in[3];
    const float* proj_b  = (const float*)d_in[4];
    const float* rpb     = (const float*)d_in[5];
    const float* norm2_g = (const float*)d_in[6];
    const float* norm2_b = (const float*)d_in[7];
    const float* mlp_w1  = (const float*)d_in[8];
    const float* mlp_b1  = (const float*)d_in[9];
    const float* mlp_w2  = (const float*)d_in[10];
    const float* mlp_b2  = (const float*)d_in[11];
    float* out = (float*)d_out;

    // precision conversions
    conv_x_k<<<TOK * CDIM / (256 * 8), 256>>>(x);
    conv_w_all<<<(S0 + S1 + S2 + S3) / (256 * 8), 256>>>(qkv_w, proj_w, mlp_w1, mlp_w2);

    // 1) QKV = gather(x) @ qkv_w + b  -> bf16 g_qkv (window order)
    gemm_bf<192, 576, 0><<<dim3(6, 1024), 128>>>(qkv_b, nullptr, nullptr);
    // 2) windowed attention (register-resident softmax) -> bf16 g_attnout
    attn_tc<<<dim3(NWIN, NHEAD), 128>>>(rpb);
    // 3) proj + scatter + residual -> fp32 g_x1
    gemm_bf<192, 192, 1><<<dim3(2, 1024), 128>>>(proj_b, x, nullptr);
    // 4) LayerNorm(g_x1) -> bf16 g_x1n
    ln_norm_k<<<TOK / 8, 256>>>(norm2_g, norm2_b);
    // 5) fc1 + GELU -> bf16 g_h
    gemm_bf<192, 768, 2><<<dim3(8, 1024), 128>>>(mlp_b1, nullptr, nullptr);
    // 6) fc2 + residual -> fp32 out
    gemm_bf<768, 192, 3><<<dim3(2, 1024), 128>>>(mlp_b2, nullptr, out);
}